// round 1
// baseline (speedup 1.0000x reference)
#include <cuda_runtime.h>
#include <cstdint>

#define NHID    128
#define KDIM    256      // 2*NHID
#define TILE_E  64       // edges per CTA tile
#define THREADS 256
#define GRID    152      // GB300 SM count; persistent 1 CTA/SM (192KB smem)

// ---------------------------------------------------------------------------
// packed fp32x2 helpers (Blackwell FFMA2 — only reachable via PTX)
// ---------------------------------------------------------------------------
__device__ __forceinline__ unsigned long long pack2(float lo, float hi) {
    unsigned long long r;
    asm("mov.b64 %0, {%1, %2};" : "=l"(r) : "f"(lo), "f"(hi));
    return r;
}
__device__ __forceinline__ void fma2(unsigned long long& d,
                                     unsigned long long a,
                                     unsigned long long b) {
    asm("fma.rn.f32x2 %0, %1, %2, %0;" : "+l"(d) : "l"(a), "l"(b));
}
__device__ __forceinline__ float2 unpack2(unsigned long long v) {
    float2 f;
    asm("mov.b64 {%0, %1}, %2;" : "=f"(f.x), "=f"(f.y) : "l"(v));
    return f;
}

// ---------------------------------------------------------------------------
// index-width autodetect: reference says int64 but JAX default x64-off makes
// them int32. If the buffer is really int32, an int64 view has a random
// nonzero high word -> value >= n_nodes. 16 probes make misdetection ~0.
// ---------------------------------------------------------------------------
__device__ int g_idx_is64;

__global__ void detect_idx_width(const long long* xi, int n_nodes) {
    int is64 = 1;
    for (int i = 0; i < 16; ++i) {
        long long v = xi[i];
        if (v < 0 || v >= (long long)n_nodes) { is64 = 0; break; }
    }
    g_idx_is64 = is64;
}

// ---------------------------------------------------------------------------
// Main fused kernel.
// SMEM: W1 [256][128] fp32 (128KB, loaded once) + ins [64][256] fp32 (64KB).
// Thread (cg = tid&31, eg = tid>>5): 8 edges (eg*8..) x 4 cols (4*cg..).
// Warp = fixed eg, all 32 cg -> x reads from smem are pure broadcasts.
// ---------------------------------------------------------------------------
extern __shared__ float smem[];

__global__ void __launch_bounds__(THREADS, 1)
mlp_decoder_kernel(const float* __restrict__ inputs,
                   const void*  __restrict__ x_idx_raw,
                   const void*  __restrict__ y_idx_raw,
                   const float* __restrict__ W1,
                   const float* __restrict__ bias1,
                   const float* __restrict__ W2,
                   const float* __restrict__ bias2,
                   float* __restrict__ out,
                   int n_edges)
{
    float* w1s = smem;                    // KDIM*NHID floats
    float* ins = smem + KDIM * NHID;      // TILE_E*KDIM floats

    const int tid = threadIdx.x;
    const int cg  = tid & 31;             // column group (4 cols)
    const int eg  = tid >> 5;             // edge group (8 edges) == warp id

    const int idx64 = g_idx_is64;
    const long long* xi64 = (const long long*)x_idx_raw;
    const long long* yi64 = (const long long*)y_idx_raw;
    const int*       xi32 = (const int*)x_idx_raw;
    const int*       yi32 = (const int*)y_idx_raw;

    // Stage W1 into SMEM once (vectorized).
    {
        const float4* W1v  = (const float4*)W1;
        float4*       w1sv = (float4*)w1s;
        for (int i = tid; i < KDIM * NHID / 4; i += THREADS)
            w1sv[i] = W1v[i];
    }

    // Per-thread epilogue constants (columns are fixed for the whole kernel).
    const float4 b1v = ((const float4*)bias1)[cg];
    const float4 w2v = ((const float4*)W2)[cg];
    const float  b2  = bias2[0];

    const int ntiles = (n_edges + TILE_E - 1) / TILE_E;
    for (int tile = blockIdx.x; tile < ntiles; tile += (int)gridDim.x) {
        const int ebase = tile * TILE_E;

        __syncthreads();   // all consumers of previous tile (and W1 stage) done

        // Gather 64 edges x 2 nodes x 128 floats -> ins[e][0:256], float4 units.
        for (int i = tid; i < TILE_E * 64; i += THREADS) {
            int e = i >> 6;            // 0..63
            int q = i & 63;            // 0..63 : q<32 from x node, else y node
            int eg_ = ebase + e;
            if (eg_ >= n_edges) eg_ = n_edges - 1;   // safe tail clamp
            long long node;
            if (idx64) node = (q < 32) ? xi64[eg_] : yi64[eg_];
            else       node = (q < 32) ? (long long)xi32[eg_] : (long long)yi32[eg_];
            float4 v = ((const float4*)(inputs + (size_t)node * NHID))[q & 31];
            ((float4*)(ins + e * KDIM))[q] = v;
        }
        __syncthreads();

        // Register-blocked GEMM: acc[2*i+p] packs cols (4cg+2p, 4cg+2p+1) of edge i.
        unsigned long long acc[16];
        #pragma unroll
        for (int i = 0; i < 16; ++i) acc[i] = 0ull;   // == {0.f, 0.f}

        const float* insE = ins + eg * 8 * KDIM;

        #pragma unroll 1
        for (int k = 0; k < KDIM; k += 4) {
            float4 xv[8];
            #pragma unroll
            for (int i = 0; i < 8; ++i)
                xv[i] = *(const float4*)(insE + i * KDIM + k);   // broadcast LDS.128
            #pragma unroll
            for (int kk = 0; kk < 4; ++kk) {
                float4 w = *(const float4*)(w1s + (k + kk) * NHID + 4 * cg);
                unsigned long long wlo = pack2(w.x, w.y);
                unsigned long long whi = pack2(w.z, w.w);
                #pragma unroll
                for (int i = 0; i < 8; ++i) {
                    float x = (kk == 0) ? xv[i].x :
                              (kk == 1) ? xv[i].y :
                              (kk == 2) ? xv[i].z : xv[i].w;
                    unsigned long long xx = pack2(x, x);
                    fma2(acc[2 * i],     xx, wlo);
                    fma2(acc[2 * i + 1], xx, whi);
                }
            }
        }

        // Epilogue: bias + relu + dot with W2 cols, warp-reduce 32 lanes/edge.
        #pragma unroll
        for (int i = 0; i < 8; ++i) {
            float2 a0 = unpack2(acc[2 * i]);
            float2 a1 = unpack2(acc[2 * i + 1]);
            float v0 = fmaxf(a0.x + b1v.x, 0.0f) * w2v.x;
            float v1 = fmaxf(a0.y + b1v.y, 0.0f) * w2v.y;
            float v2 = fmaxf(a1.x + b1v.z, 0.0f) * w2v.z;
            float v3 = fmaxf(a1.y + b1v.w, 0.0f) * w2v.w;
            float s = (v0 + v1) + (v2 + v3);
            #pragma unroll
            for (int off = 16; off; off >>= 1)
                s += __shfl_xor_sync(0xffffffffu, s, off);
            if (cg == 0) {
                int eg_ = ebase + eg * 8 + i;
                if (eg_ < n_edges)
                    out[eg_] = 1.0f / (1.0f + __expf(-(s + b2)));
            }
        }
    }
}

// ---------------------------------------------------------------------------
// kernel_launch — graph-capturable, allocation-free.
// Inputs (metadata order): inputs, x_idx, y_idx, W1, bias1, W2, bias2.
// ---------------------------------------------------------------------------
extern "C" void kernel_launch(void* const* d_in, const int* in_sizes, int n_in,
                              void* d_out, int out_size)
{
    const float* inputs = (const float*)d_in[0];
    const void*  x_idx  = d_in[1];
    const void*  y_idx  = d_in[2];
    const float* W1     = (const float*)d_in[3];
    const float* bias1  = (const float*)d_in[4];
    const float* W2     = (const float*)d_in[5];
    const float* bias2  = (const float*)d_in[6];
    float* out = (float*)d_out;

    const int n_edges = in_sizes[1];
    const int n_nodes = in_sizes[0] / NHID;

    detect_idx_width<<<1, 1>>>((const long long*)x_idx, n_nodes);

    size_t smem_bytes = (size_t)(KDIM * NHID + TILE_E * KDIM) * sizeof(float); // 196608
    cudaFuncSetAttribute(mlp_decoder_kernel,
                         cudaFuncAttributeMaxDynamicSharedMemorySize,
                         (int)smem_bytes);

    mlp_decoder_kernel<<<GRID, THREADS, smem_bytes>>>(
        inputs, x_idx, y_idx, W1, bias1, W2, bias2, out, n_edges);
}

// round 4
// speedup vs baseline: 2.7177x; 2.7177x over previous
#include <cuda_runtime.h>
#include <cstdint>

#define NHID     128
#define KDIM     256
#define TILE_M   128
#define THREADS  256
#define GRID     152
#define NKS      32      // total k8 steps (KDIM/8)
#define CKS      8       // k8 steps per chunk (Kc=64)
#define NCHUNKS  4

// ---------------- smem layout (bytes) ----------------
// B frags: [ntile 16][kstep 32][lane 32] float2      = 131072
// A frags: 2 x [mtile 8][ks 8][lane 32] float4       = 2 x 32768
// sxi/syi: 128 int each; sred: 128 rows x 4 floats
#define OFF_BFRAG  0
#define OFF_AFRAG  131072
#define AFRAG_BUF  32768
#define OFF_SXI    196608
#define OFF_SYI    197120
#define OFF_SRED   197632
#define SMEM_TOTAL 199680

// ---------------- PTX helpers ----------------
__device__ __forceinline__ uint32_t smem_u32(const void* p) {
    uint32_t a;
    asm("{ .reg .u64 t; cvta.to.shared.u64 t, %1; cvt.u32.u64 %0, t; }" : "=r"(a) : "l"(p));
    return a;
}
__device__ __forceinline__ void cp4(uint32_t dst, const void* src) {
    asm volatile("cp.async.ca.shared.global [%0], [%1], 4;" :: "r"(dst), "l"(src));
}
__device__ __forceinline__ void cp_commit() {
    asm volatile("cp.async.commit_group;" ::: "memory");
}
template <int N>
__device__ __forceinline__ void cp_wait() {
    asm volatile("cp.async.wait_group %0;" :: "n"(N) : "memory");
}
// mma.sync m16n8k8 tf32 (arch-neutral PTX; no sm_103a-gated features)
__device__ __forceinline__ void mma_tf32(float& c0, float& c1, float& c2, float& c3,
                                         uint32_t a0, uint32_t a1, uint32_t a2, uint32_t a3,
                                         uint32_t b0, uint32_t b1) {
    asm volatile("mma.sync.aligned.m16n8k8.row.col.f32.tf32.tf32.f32 "
                 "{%0,%1,%2,%3}, {%4,%5,%6,%7}, {%8,%9}, {%0,%1,%2,%3};"
                 : "+f"(c0), "+f"(c1), "+f"(c2), "+f"(c3)
                 : "r"(a0), "r"(a1), "r"(a2), "r"(a3), "r"(b0), "r"(b1));
}

// ---------------- index width autodetect ----------------
__device__ int g_idx_is64;
__global__ void detect_idx_width(const long long* xi, int n_nodes) {
    int is64 = 1;
    for (int i = 0; i < 16; ++i) {
        long long v = xi[i];
        if (v < 0 || v >= (long long)n_nodes) { is64 = 0; break; }
    }
    g_idx_is64 = is64;
}

// ---------------- main kernel ----------------
extern __shared__ char smem[];

__global__ void __launch_bounds__(THREADS, 1)
mlp_decoder_mma(const float* __restrict__ inputs,
                const void*  __restrict__ x_idx_raw,
                const void*  __restrict__ y_idx_raw,
                const float* __restrict__ W1,
                const float* __restrict__ bias1,
                const float* __restrict__ W2,
                const float* __restrict__ bias2,
                float* __restrict__ out,
                int n_edges)
{
    const int tid  = threadIdx.x;
    const int wid  = tid >> 5;
    const int lane = tid & 31;
    const int g    = lane >> 2;     // groupID (fragment row base)
    const int t    = lane & 3;      // threadID_in_group (fragment col base)
    const int mw   = wid >> 2;      // m-group: mtiles mw*4 .. mw*4+3
    const int nw   = wid & 3;       // n-group: ntiles nw*4 .. nw*4+3
    const uint32_t sbase = smem_u32(smem);

    int* sxi = (int*)(smem + OFF_SXI);
    int* syi = (int*)(smem + OFF_SYI);
    float* sred = (float*)(smem + OFF_SRED);

    const int idx64 = g_idx_is64;
    const long long* xi64 = (const long long*)x_idx_raw;
    const long long* yi64 = (const long long*)y_idx_raw;
    const int*       xi32 = (const int*)x_idx_raw;
    const int*       yi32 = (const int*)y_idx_raw;

    // ---- one-time: stage W1 into B fragment layout ----
    // slot i: nt = i>>10, ks = (i>>5)&31, l = i&31; gg=l>>2, tt=l&3
    // b0 = W1[ks*8+tt][nt*8+gg], b1 = W1[ks*8+tt+4][nt*8+gg]
    for (int i = tid; i < 16 * 32 * 32; i += THREADS) {
        int nt = i >> 10, ks = (i >> 5) & 31, l = i & 31;
        int gg = l >> 2, tt = l & 3;
        int k0 = ks * 8 + tt, n = nt * 8 + gg;
        float2 b;
        b.x = W1[k0 * NHID + n];
        b.y = W1[(k0 + 4) * NHID + n];
        *(float2*)(smem + OFF_BFRAG + (size_t)i * 8) = b;
    }

    // ---- per-thread epilogue constants (columns fixed) ----
    float b1r[8], w2r[8];
    #pragma unroll
    for (int nt = 0; nt < 4; ++nt) {
        int col = (nw * 4 + nt) * 8 + t * 2;
        b1r[nt * 2]     = bias1[col];
        b1r[nt * 2 + 1] = bias1[col + 1];
        w2r[nt * 2]     = W2[col];
        w2r[nt * 2 + 1] = W2[col + 1];
    }
    const float b2 = bias2[0];

    __syncthreads();

    const int ntiles = (n_edges + TILE_M - 1) / TILE_M;
    for (int tile = blockIdx.x; tile < ntiles; tile += GRID) {
        const int ebase = tile * TILE_M;

        // stage clamped indices
        for (int i = tid; i < TILE_M; i += THREADS) {
            int e = ebase + i; if (e >= n_edges) e = n_edges - 1;
            sxi[i] = idx64 ? (int)xi64[e] : xi32[e];
            syi[i] = idx64 ? (int)yi64[e] : yi32[e];
        }
        __syncthreads();

        // gather issue for chunk c into buffer (c&1), cp.async 4B into frag slots
        auto issue_chunk = [&](int c) {
            const int* idxarr = (c < 2) ? sxi : syi;
            const int kbase = (c & 1) * 64;
            const uint32_t abuf = sbase + OFF_AFRAG + (uint32_t)(c & 1) * AFRAG_BUF;
            for (int i = tid; i < 8 * 8 * 32; i += THREADS) {
                int mt = i >> 8, ks = (i >> 5) & 7, l = i & 31;
                int gg = l >> 2, tt = l & 3;
                int e0 = mt * 16 + gg;
                const float* p0 = inputs + (size_t)idxarr[e0]     * NHID + kbase + ks * 8 + tt;
                const float* p1 = inputs + (size_t)idxarr[e0 + 8] * NHID + kbase + ks * 8 + tt;
                uint32_t dst = abuf + (uint32_t)i * 16;
                cp4(dst,      p0);       // a0: row g,   col t
                cp4(dst + 4,  p1);       // a1: row g+8, col t
                cp4(dst + 8,  p0 + 4);   // a2: row g,   col t+4
                cp4(dst + 12, p1 + 4);   // a3: row g+8, col t+4
            }
        };

        issue_chunk(0); cp_commit();

        float acc[4][4][4];
        #pragma unroll
        for (int mt = 0; mt < 4; ++mt)
            #pragma unroll
            for (int nt = 0; nt < 4; ++nt)
                #pragma unroll
                for (int r = 0; r < 4; ++r) acc[mt][nt][r] = 0.0f;

        for (int c = 0; c < NCHUNKS; ++c) {
            if (c < NCHUNKS - 1) { issue_chunk(c + 1); cp_commit(); }
            if (c < NCHUNKS - 1) cp_wait<1>(); else cp_wait<0>();
            __syncthreads();

            const char* abuf = smem + OFF_AFRAG + (size_t)(c & 1) * AFRAG_BUF;

            #pragma unroll
            for (int ks = 0; ks < CKS; ++ks) {
                const int gks = c * CKS + ks;
                uint2 bf[4];
                #pragma unroll
                for (int nt = 0; nt < 4; ++nt)
                    bf[nt] = *(const uint2*)(smem + OFF_BFRAG +
                              (size_t)(((nw * 4 + nt) * 32 + gks) * 32 + lane) * 8);
                uint4 af[4];
                #pragma unroll
                for (int mt = 0; mt < 4; ++mt)
                    af[mt] = *(const uint4*)(abuf +
                              (size_t)(((mw * 4 + mt) * CKS + ks) * 32 + lane) * 16);
                #pragma unroll
                for (int mt = 0; mt < 4; ++mt)
                    #pragma unroll
                    for (int nt = 0; nt < 4; ++nt)
                        mma_tf32(acc[mt][nt][0], acc[mt][nt][1],
                                 acc[mt][nt][2], acc[mt][nt][3],
                                 af[mt].x, af[mt].y, af[mt].z, af[mt].w,
                                 bf[nt].x, bf[nt].y);
            }
            __syncthreads();   // all warps done with buf (c&1) before it is refilled
        }

        // ---- epilogue: relu + W2 dot, reduce over t then over n-groups ----
        #pragma unroll
        for (int mt = 0; mt < 4; ++mt) {
            #pragma unroll
            for (int h = 0; h < 2; ++h) {
                float s = 0.0f;
                #pragma unroll
                for (int nt = 0; nt < 4; ++nt) {
                    float ca = acc[mt][nt][h * 2];
                    float cb = acc[mt][nt][h * 2 + 1];
                    s += fmaxf(ca + b1r[nt * 2],     0.0f) * w2r[nt * 2];
                    s += fmaxf(cb + b1r[nt * 2 + 1], 0.0f) * w2r[nt * 2 + 1];
                }
                s += __shfl_xor_sync(0xffffffffu, s, 1);
                s += __shfl_xor_sync(0xffffffffu, s, 2);
                if (t == 0) {
                    int row = (mw * 4 + mt) * 16 + g + h * 8;
                    sred[row * 4 + nw] = s;
                }
            }
        }
        __syncthreads();

        if (tid < TILE_M) {
            float4 v = *(const float4*)(sred + tid * 4);
            float sum = (v.x + v.y) + (v.z + v.w) + b2;
            int e = ebase + tid;
            if (e < n_edges)
                out[e] = 1.0f / (1.0f + __expf(-sum));
        }
        __syncthreads();   // sred consumed before next tile's epilogue writes
    }
}

// ---------------- launch ----------------
extern "C" void kernel_launch(void* const* d_in, const int* in_sizes, int n_in,
                              void* d_out, int out_size)
{
    const float* inputs = (const float*)d_in[0];
    const void*  x_idx  = d_in[1];
    const void*  y_idx  = d_in[2];
    const float* W1     = (const float*)d_in[3];
    const float* bias1  = (const float*)d_in[4];
    const float* W2     = (const float*)d_in[5];
    const float* bias2  = (const float*)d_in[6];
    float* out = (float*)d_out;

    const int n_edges = in_sizes[1];
    const int n_nodes = in_sizes[0] / NHID;

    detect_idx_width<<<1, 1>>>((const long long*)x_idx, n_nodes);

    cudaFuncSetAttribute(mlp_decoder_mma,
                         cudaFuncAttributeMaxDynamicSharedMemorySize, SMEM_TOTAL);
    mlp_decoder_mma<<<GRID, THREADS, SMEM_TOTAL>>>(
        inputs, x_idx, y_idx, W1, bias1, W2, bias2, out, n_edges);
}

// round 5
// speedup vs baseline: 4.1307x; 1.5199x over previous
#include <cuda_runtime.h>
#include <cstdint>

#define NHID     128
#define KDIM     256
#define TILE_M   128
#define THREADS  256
#define GRID     152
#define CKS      8       // k8 steps per chunk (Kc=64)
#define NCHUNKS  4

// ---------------- smem layout (bytes) ----------------
// B frags : [ntile 16][kstep 32][lane 32] float2            = 131072
// A stage : 2 x [edge 128][68 floats] (64 data + 4 pad)     = 2 x 34816
#define OFF_BFRAG  0
#define OFF_A0     131072
#define OFF_A1     165888
#define AROW       272            // bytes per padded row (68 floats)
#define OFF_SXI    200704
#define OFF_SYI    201216
#define OFF_SRED   201728
#define SMEM_TOTAL 203776

// ---------------- PTX helpers ----------------
__device__ __forceinline__ uint32_t smem_u32(const void* p) {
    uint32_t a;
    asm("{ .reg .u64 t; cvta.to.shared.u64 t, %1; cvt.u32.u64 %0, t; }" : "=r"(a) : "l"(p));
    return a;
}
__device__ __forceinline__ void cp16(uint32_t dst, const void* src) {
    asm volatile("cp.async.cg.shared.global [%0], [%1], 16;" :: "r"(dst), "l"(src));
}
__device__ __forceinline__ void cp_commit() {
    asm volatile("cp.async.commit_group;" ::: "memory");
}
template <int N>
__device__ __forceinline__ void cp_wait() {
    asm volatile("cp.async.wait_group %0;" :: "n"(N) : "memory");
}
__device__ __forceinline__ void mma_tf32(float& c0, float& c1, float& c2, float& c3,
                                         uint32_t a0, uint32_t a1, uint32_t a2, uint32_t a3,
                                         uint32_t b0, uint32_t b1) {
    asm volatile("mma.sync.aligned.m16n8k8.row.col.f32.tf32.tf32.f32 "
                 "{%0,%1,%2,%3}, {%4,%5,%6,%7}, {%8,%9}, {%0,%1,%2,%3};"
                 : "+f"(c0), "+f"(c1), "+f"(c2), "+f"(c3)
                 : "r"(a0), "r"(a1), "r"(a2), "r"(a3), "r"(b0), "r"(b1));
}
__device__ __forceinline__ uint32_t lds32(uint32_t addr) {
    uint32_t v;
    asm volatile("ld.shared.b32 %0, [%1];" : "=r"(v) : "r"(addr));
    return v;
}

// ---------------- index width autodetect ----------------
__device__ int g_idx_is64;
__global__ void detect_idx_width(const long long* xi, int n_nodes) {
    int is64 = 1;
    for (int i = 0; i < 16; ++i) {
        long long v = xi[i];
        if (v < 0 || v >= (long long)n_nodes) { is64 = 0; break; }
    }
    g_idx_is64 = is64;
}

// ---------------- main kernel ----------------
extern __shared__ char smem[];

__global__ void __launch_bounds__(THREADS, 1)
mlp_decoder_mma(const float* __restrict__ inputs,
                const void*  __restrict__ x_idx_raw,
                const void*  __restrict__ y_idx_raw,
                const float* __restrict__ W1,
                const float* __restrict__ bias1,
                const float* __restrict__ W2,
                const float* __restrict__ bias2,
                float* __restrict__ out,
                int n_edges)
{
    const int tid  = threadIdx.x;
    const int wid  = tid >> 5;
    const int lane = tid & 31;
    const int g    = lane >> 2;     // fragment row base
    const int t    = lane & 3;      // fragment col base
    const int mw   = wid >> 2;      // m-group (0..1): mtiles mw*4..mw*4+3
    const int nw   = wid & 3;       // n-group (0..3): ntiles nw*4..nw*4+3
    const uint32_t sbase = smem_u32(smem);

    int* sxi = (int*)(smem + OFF_SXI);
    int* syi = (int*)(smem + OFF_SYI);
    float* sred = (float*)(smem + OFF_SRED);

    const int idx64 = g_idx_is64;
    const long long* xi64 = (const long long*)x_idx_raw;
    const long long* yi64 = (const long long*)y_idx_raw;
    const int*       xi32 = (const int*)x_idx_raw;
    const int*       yi32 = (const int*)y_idx_raw;

    // ---- one-time: stage W1 into B fragment layout ----
    // slot i: nt=i>>10, ks=(i>>5)&31, l=i&31 (gg=l>>2, tt=l&3)
    // b0 = W1[ks*8+tt][nt*8+gg], b1 = W1[ks*8+tt+4][nt*8+gg]
    for (int i = tid; i < 16 * 32 * 32; i += THREADS) {
        int nt = i >> 10, ks = (i >> 5) & 31, l = i & 31;
        int gg = l >> 2, tt = l & 3;
        int k0 = ks * 8 + tt, n = nt * 8 + gg;
        float2 b;
        b.x = W1[k0 * NHID + n];
        b.y = W1[(k0 + 4) * NHID + n];
        *(float2*)(smem + OFF_BFRAG + (size_t)i * 8) = b;
    }

    // ---- per-thread epilogue constants ----
    float b1r[8], w2r[8];
    #pragma unroll
    for (int nt = 0; nt < 4; ++nt) {
        int col = (nw * 4 + nt) * 8 + t * 2;
        b1r[nt * 2]     = bias1[col];
        b1r[nt * 2 + 1] = bias1[col + 1];
        w2r[nt * 2]     = W2[col];
        w2r[nt * 2 + 1] = W2[col + 1];
    }
    const float b2 = bias2[0];

    __syncthreads();

    const int ntiles = (n_edges + TILE_M - 1) / TILE_M;
    for (int tile = blockIdx.x; tile < ntiles; tile += GRID) {
        const int ebase = tile * TILE_M;

        for (int i = tid; i < TILE_M; i += THREADS) {
            int e = ebase + i; if (e >= n_edges) e = n_edges - 1;
            sxi[i] = idx64 ? (int)xi64[e] : xi32[e];
            syi[i] = idx64 ? (int)yi64[e] : yi32[e];
        }
        __syncthreads();

        // gather chunk c into K-major padded stage, 16B cp.async, coalesced
        auto issue_chunk = [&](int c) {
            const int* idxarr = (c < 2) ? sxi : syi;
            const int kbase = (c & 1) * 64;
            const uint32_t abuf = sbase + ((c & 1) ? OFF_A1 : OFF_A0);
            #pragma unroll
            for (int r = 0; r < 8; ++r) {               // 2048 / 256
                int i = r * THREADS + tid;
                int e = i >> 4, q = i & 15;
                const float* src = inputs + (size_t)idxarr[e] * NHID + kbase + q * 4;
                cp16(abuf + e * AROW + q * 16, src);
            }
        };

        issue_chunk(0); cp_commit();

        float acc[4][4][4];
        #pragma unroll
        for (int mt = 0; mt < 4; ++mt)
            #pragma unroll
            for (int nt = 0; nt < 4; ++nt)
                #pragma unroll
                for (int r = 0; r < 4; ++r) acc[mt][nt][r] = 0.0f;

        for (int c = 0; c < NCHUNKS; ++c) {
            if (c < NCHUNKS - 1) { issue_chunk(c + 1); cp_commit(); cp_wait<1>(); }
            else                 { cp_wait<0>(); }
            __syncthreads();

            const uint32_t abuf = sbase + ((c & 1) ? OFF_A1 : OFF_A0);
            // per-thread row bases: rows e0+g and e0+g+8 of mtiles mw*4..mw*4+3
            // A[e][k] at abuf + e*272 + k*4 ; conflict-free (68 mod 32 = 4)
            const uint32_t rbase = abuf + (uint32_t)(mw * 4) * 16 * AROW
                                 + (uint32_t)g * AROW + (uint32_t)t * 4;

            #pragma unroll
            for (int ks = 0; ks < CKS; ++ks) {
                const int gks = c * CKS + ks;
                uint2 bf[4];
                #pragma unroll
                for (int nt = 0; nt < 4; ++nt)
                    bf[nt] = *(const uint2*)(smem + OFF_BFRAG +
                              (size_t)(((nw * 4 + nt) * 32 + gks) * 32 + lane) * 8);
                #pragma unroll
                for (int mt = 0; mt < 4; ++mt) {
                    const uint32_t rl = rbase + (uint32_t)mt * 16 * AROW + (uint32_t)ks * 32;
                    uint32_t a0 = lds32(rl);                    // [g,    ks*8+t]
                    uint32_t a1 = lds32(rl + 8 * AROW);         // [g+8,  ks*8+t]
                    uint32_t a2 = lds32(rl + 16);               // [g,    ks*8+t+4]
                    uint32_t a3 = lds32(rl + 8 * AROW + 16);    // [g+8,  ks*8+t+4]
                    #pragma unroll
                    for (int nt = 0; nt < 4; ++nt)
                        mma_tf32(acc[mt][nt][0], acc[mt][nt][1],
                                 acc[mt][nt][2], acc[mt][nt][3],
                                 a0, a1, a2, a3, bf[nt].x, bf[nt].y);
                }
            }
            __syncthreads();   // buf consumed before refill
        }

        // ---- epilogue: relu + W2 dot, reduce t-lanes then n-groups ----
        #pragma unroll
        for (int mt = 0; mt < 4; ++mt) {
            #pragma unroll
            for (int h = 0; h < 2; ++h) {
                float s = 0.0f;
                #pragma unroll
                for (int nt = 0; nt < 4; ++nt) {
                    float ca = acc[mt][nt][h * 2];
                    float cb = acc[mt][nt][h * 2 + 1];
                    s += fmaxf(ca + b1r[nt * 2],     0.0f) * w2r[nt * 2];
                    s += fmaxf(cb + b1r[nt * 2 + 1], 0.0f) * w2r[nt * 2 + 1];
                }
                s += __shfl_xor_sync(0xffffffffu, s, 1);
                s += __shfl_xor_sync(0xffffffffu, s, 2);
                if (t == 0) {
                    int row = (mw * 4 + mt) * 16 + g + h * 8;
                    sred[row * 4 + nw] = s;
                }
            }
        }
        __syncthreads();

        if (tid < TILE_M) {
            float4 v = *(const float4*)(sred + tid * 4);
            float sum = (v.x + v.y) + (v.z + v.w) + b2;
            int e = ebase + tid;
            if (e < n_edges)
                out[e] = 1.0f / (1.0f + __expf(-sum));
        }
        __syncthreads();
    }
}

// ---------------- launch ----------------
extern "C" void kernel_launch(void* const* d_in, const int* in_sizes, int n_in,
                              void* d_out, int out_size)
{
    const float* inputs = (const float*)d_in[0];
    const void*  x_idx  = d_in[1];
    const void*  y_idx  = d_in[2];
    const float* W1     = (const float*)d_in[3];
    const float* bias1  = (const float*)d_in[4];
    const float* W2     = (const float*)d_in[5];
    const float* bias2  = (const float*)d_in[6];
    float* out = (float*)d_out;

    const int n_edges = in_sizes[1];
    const int n_nodes = in_sizes[0] / NHID;

    detect_idx_width<<<1, 1>>>((const long long*)x_idx, n_nodes);

    cudaFuncSetAttribute(mlp_decoder_mma,
                         cudaFuncAttributeMaxDynamicSharedMemorySize, SMEM_TOTAL);
    mlp_decoder_mma<<<GRID, THREADS, SMEM_TOTAL>>>(
        inputs, x_idx, y_idx, W1, bias1, W2, bias2, out, n_edges);
}

// round 6
// speedup vs baseline: 5.7440x; 1.3906x over previous
#include <cuda_runtime.h>
#include <cuda_fp16.h>
#include <cstdint>

#define NHID     128
#define KDIM     256
#define TILE_M   128
#define THREADS  256
#define GRID     152
#define NCHUNKS  4       // 64-wide k chunks

// ---------------- smem layout (bytes) ----------------
// B frag fp16 : [nt 16][gks16 16][lane 32][8B]  = 65536
// A frag fp16 : 2 x [mt 8][ks16 4][lane 32][16B] = 2 x 16384
#define OFF_BFRAG  0
#define OFF_AF0    65536
#define OFF_AF1    81920
#define OFF_SXI    98304
#define OFF_SYI    98816
#define OFF_SRED   99328
#define SMEM_TOTAL 101376

// ---------------- PTX helpers ----------------
__device__ __forceinline__ uint32_t smem_u32(const void* p) {
    uint32_t a;
    asm("{ .reg .u64 t; cvta.to.shared.u64 t, %1; cvt.u32.u64 %0, t; }" : "=r"(a) : "l"(p));
    return a;
}
__device__ __forceinline__ uint32_t f2h2(float lo, float hi) {   // {lo, hi} packed
    uint32_t v;
    asm("cvt.rn.f16x2.f32 %0, %1, %2;" : "=r"(v) : "f"(hi), "f"(lo));
    return v;
}
__device__ __forceinline__ void sts32(uint32_t addr, uint32_t v) {
    asm volatile("st.shared.b32 [%0], %1;" :: "r"(addr), "r"(v) : "memory");
}
__device__ __forceinline__ void mma_f16(float& c0, float& c1, float& c2, float& c3,
                                        uint32_t a0, uint32_t a1, uint32_t a2, uint32_t a3,
                                        uint32_t b0, uint32_t b1) {
    asm volatile("mma.sync.aligned.m16n8k16.row.col.f32.f16.f16.f32 "
                 "{%0,%1,%2,%3}, {%4,%5,%6,%7}, {%8,%9}, {%0,%1,%2,%3};"
                 : "+f"(c0), "+f"(c1), "+f"(c2), "+f"(c3)
                 : "r"(a0), "r"(a1), "r"(a2), "r"(a3), "r"(b0), "r"(b1));
}

// ---------------- index width autodetect ----------------
__device__ int g_idx_is64;
__global__ void detect_idx_width(const long long* xi, int n_nodes) {
    int is64 = 1;
    for (int i = 0; i < 16; ++i) {
        long long v = xi[i];
        if (v < 0 || v >= (long long)n_nodes) { is64 = 0; break; }
    }
    g_idx_is64 = is64;
}

// ---------------- main kernel ----------------
extern __shared__ char smem[];

__global__ void __launch_bounds__(THREADS, 1)
mlp_decoder_h2(const float* __restrict__ inputs,
               const void*  __restrict__ x_idx_raw,
               const void*  __restrict__ y_idx_raw,
               const float* __restrict__ W1,
               const float* __restrict__ bias1,
               const float* __restrict__ W2,
               const float* __restrict__ bias2,
               float* __restrict__ out,
               int n_edges)
{
    const int tid  = threadIdx.x;
    const int wid  = tid >> 5;
    const int lane = tid & 31;
    const int g    = lane >> 2;
    const int t    = lane & 3;
    const int mw   = wid >> 2;      // m-group (0..1): mtiles mw*4..+3
    const int nw   = wid & 3;       // n-group (0..3): ntiles nw*4..+3
    const uint32_t sbase = smem_u32(smem);

    int* sxi = (int*)(smem + OFF_SXI);
    int* syi = (int*)(smem + OFF_SYI);
    float* sred = (float*)(smem + OFF_SRED);

    const int idx64 = g_idx_is64;
    const long long* xi64 = (const long long*)x_idx_raw;
    const long long* yi64 = (const long long*)y_idx_raw;
    const int*       xi32 = (const int*)x_idx_raw;
    const int*       yi32 = (const int*)y_idx_raw;

    // ---- one-time: W1 -> fp16 B fragment table ----
    // slot i: nt=i>>9, gks16=(i>>5)&15, l=i&31 (gg=l>>2, tt=l&3)
    // b0={W1[k0][n],W1[k0+1][n]}, b1={W1[k0+8][n],W1[k0+9][n]}, k0=gks16*16+2tt
    for (int i = tid; i < 16 * 16 * 32; i += THREADS) {
        int nt = i >> 9, ks = (i >> 5) & 15, l = i & 31;
        int gg = l >> 2, tt = l & 3;
        int k0 = ks * 16 + 2 * tt, n = nt * 8 + gg;
        uint32_t b0 = f2h2(W1[k0 * NHID + n],       W1[(k0 + 1) * NHID + n]);
        uint32_t b1 = f2h2(W1[(k0 + 8) * NHID + n], W1[(k0 + 9) * NHID + n]);
        sts32(sbase + OFF_BFRAG + (uint32_t)i * 8,     b0);
        sts32(sbase + OFF_BFRAG + (uint32_t)i * 8 + 4, b1);
    }

    // ---- per-thread epilogue constants (cols t*2, t*2+1 of each nt) ----
    float b1r[8], w2r[8];
    #pragma unroll
    for (int nt = 0; nt < 4; ++nt) {
        int col = (nw * 4 + nt) * 8 + t * 2;
        b1r[nt * 2]     = bias1[col];
        b1r[nt * 2 + 1] = bias1[col + 1];
        w2r[nt * 2]     = W2[col];
        w2r[nt * 2 + 1] = W2[col + 1];
    }
    const float b2 = bias2[0];

    __syncthreads();

    // per-thread gather geometry: i = r*256+tid -> e=i>>4, q=i&15
    const int ge = tid >> 4;        // base edge (r adds 16 per step)
    const int gq = tid & 15;        // float4 index within 64-float chunk

    const int ntiles = (n_edges + TILE_M - 1) / TILE_M;
    for (int tile = blockIdx.x; tile < ntiles; tile += GRID) {
        const int ebase = tile * TILE_M;

        for (int i = tid; i < TILE_M; i += THREADS) {
            int e = ebase + i; if (e >= n_edges) e = n_edges - 1;
            sxi[i] = idx64 ? (int)xi64[e] : xi32[e];
            syi[i] = idx64 ? (int)yi64[e] : yi32[e];
        }
        __syncthreads();

        float4 pf[8];
        // prefetch chunk c into pf registers (LDG.128, coalesced 256B per edge)
        auto prefetch = [&](int c) {
            const int* idxarr = (c < 2) ? sxi : syi;
            const int kbase = (c & 1) * 64;
            #pragma unroll
            for (int r = 0; r < 8; ++r) {
                int e = ge + r * 16;
                pf[r] = *(const float4*)(inputs + (size_t)idxarr[e] * NHID + kbase + gq * 4);
            }
        };
        // convert + scatter pf into fp16 A fragment buffer for chunk c
        auto sts_chunk = [&](int c) {
            const uint32_t abuf = sbase + ((c & 1) ? OFF_AF1 : OFF_AF0);
            const int ks16 = gq >> 2;          // 0..3
            const int kk0  = (gq & 3) * 4;     // 0,4,8,12
            const int t1   = (kk0 & 7) >> 1;   // 0 or 2
            const int rhi  = (kk0 >= 8) ? 2 : 0;
            #pragma unroll
            for (int r = 0; r < 8; ++r) {
                int e = ge + r * 16;
                int mt = e >> 4, rr = e & 15;
                int gg = rr & 7, hi = rr >> 3;
                uint32_t addr = abuf + (uint32_t)(((mt * 4 + ks16) * 32 + (gg * 4 + t1)) * 16
                                                  + (hi + rhi) * 4);
                sts32(addr,      f2h2(pf[r].x, pf[r].y));
                sts32(addr + 16, f2h2(pf[r].z, pf[r].w));
            }
        };

        prefetch(0);
        sts_chunk(0);
        __syncthreads();

        float acc[4][4][4];
        #pragma unroll
        for (int mt = 0; mt < 4; ++mt)
            #pragma unroll
            for (int nt = 0; nt < 4; ++nt)
                #pragma unroll
                for (int r = 0; r < 4; ++r) acc[mt][nt][r] = 0.0f;

        for (int c = 0; c < NCHUNKS; ++c) {
            if (c < NCHUNKS - 1) prefetch(c + 1);   // LDG in flight during MMA

            const uint32_t abuf = sbase + ((c & 1) ? OFF_AF1 : OFF_AF0);
            #pragma unroll
            for (int ks = 0; ks < 4; ++ks) {
                const int gks = c * 4 + ks;
                uint2 bf[4];
                #pragma unroll
                for (int nt = 0; nt < 4; ++nt)
                    bf[nt] = *(const uint2*)(smem + OFF_BFRAG +
                              (size_t)(((nw * 4 + nt) * 16 + gks) * 32 + lane) * 8);
                #pragma unroll
                for (int mt = 0; mt < 4; ++mt) {
                    uint4 af = *(const uint4*)(smem +
                              (abuf - sbase) + (size_t)(((mw * 4 + mt) * 4 + ks) * 32 + lane) * 16);
                    #pragma unroll
                    for (int nt = 0; nt < 4; ++nt)
                        mma_f16(acc[mt][nt][0], acc[mt][nt][1],
                                acc[mt][nt][2], acc[mt][nt][3],
                                af.x, af.y, af.z, af.w, bf[nt].x, bf[nt].y);
                }
            }

            if (c < NCHUNKS - 1) {
                sts_chunk(c + 1);     // waits on pf scoreboard (mostly drained)
                __syncthreads();      // buffer published before anyone reads it
            }
        }

        // ---- epilogue: relu + W2 dot, reduce t-lanes then n-groups ----
        #pragma unroll
        for (int mt = 0; mt < 4; ++mt) {
            #pragma unroll
            for (int h = 0; h < 2; ++h) {
                float s = 0.0f;
                #pragma unroll
                for (int nt = 0; nt < 4; ++nt) {
                    float ca = acc[mt][nt][h * 2];
                    float cb = acc[mt][nt][h * 2 + 1];
                    s += fmaxf(ca + b1r[nt * 2],     0.0f) * w2r[nt * 2];
                    s += fmaxf(cb + b1r[nt * 2 + 1], 0.0f) * w2r[nt * 2 + 1];
                }
                s += __shfl_xor_sync(0xffffffffu, s, 1);
                s += __shfl_xor_sync(0xffffffffu, s, 2);
                if (t == 0) {
                    int row = (mw * 4 + mt) * 16 + g + h * 8;
                    sred[row * 4 + nw] = s;
                }
            }
        }
        __syncthreads();

        if (tid < TILE_M) {
            float4 v = *(const float4*)(sred + tid * 4);
            float sum = (v.x + v.y) + (v.z + v.w) + b2;
            int e = ebase + tid;
            if (e < n_edges)
                out[e] = 1.0f / (1.0f + __expf(-sum));
        }
        __syncthreads();
    }
}

// ---------------- launch ----------------
extern "C" void kernel_launch(void* const* d_in, const int* in_sizes, int n_in,
                              void* d_out, int out_size)
{
    const float* inputs = (const float*)d_in[0];
    const void*  x_idx  = d_in[1];
    const void*  y_idx  = d_in[2];
    const float* W1     = (const float*)d_in[3];
    const float* bias1  = (const float*)d_in[4];
    const float* W2     = (const float*)d_in[5];
    const float* bias2  = (const float*)d_in[6];
    float* out = (float*)d_out;

    const int n_edges = in_sizes[1];
    const int n_nodes = in_sizes[0] / NHID;

    detect_idx_width<<<1, 1>>>((const long long*)x_idx, n_nodes);

    cudaFuncSetAttribute(mlp_decoder_h2,
                         cudaFuncAttributeMaxDynamicSharedMemorySize, SMEM_TOTAL);
    mlp_decoder_h2<<<GRID, THREADS, SMEM_TOTAL>>>(
        inputs, x_idx, y_idx, W1, bias1, W2, bias2, out, n_edges);
}